// round 16
// baseline (speedup 1.0000x reference)
#include <cuda_runtime.h>
#include <cuda_fp16.h>
#include <cstdint>
#include <math.h>

#define EPSV 1e-5f

// ---------------- scratch (device globals; no allocs allowed) ----------------
__device__ float g_tp[16384 * 512];              // 32 MB theta||phi (fp32)
__device__ __half g_xhi[16384 * 1024];           // X hi  [b*c][p]
__device__ __half g_whi[512 * 1024];             // w1||w2 hi
__device__ __half g_wlo[512 * 1024];             // w1||w2 lo (residual)
__device__ __half g_w3hi[512 * 512];
__device__ float g_xe[16384];
__device__ float g_u[8192];
__device__ float g_v[8192];

__device__ __forceinline__ uint32_t smem_u32(const void* p) {
    uint32_t a;
    asm("{ .reg .u64 t; cvta.to.shared.u64 t, %1; cvt.u32.u64 %0, t; }" : "=r"(a) : "l"(p));
    return a;
}

#define LDSM4(R, addr) \
    asm volatile("ldmatrix.sync.aligned.m8n8.x4.shared.b16 {%0,%1,%2,%3}, [%4];" \
                 : "=r"((R)[0]), "=r"((R)[1]), "=r"((R)[2]), "=r"((R)[3]) : "r"(addr))

#define LDSM4T(R, addr) \
    asm volatile("ldmatrix.sync.aligned.m8n8.x4.trans.shared.b16 {%0,%1,%2,%3}, [%4];" \
                 : "=r"((R)[0]), "=r"((R)[1]), "=r"((R)[2]), "=r"((R)[3]) : "r"(addr))

#define MMA(D, A, b0, b1) \
    asm volatile("mma.sync.aligned.m16n8k16.row.col.f32.f16.f16.f32 " \
                 "{%0,%1,%2,%3},{%4,%5,%6,%7},{%8,%9},{%0,%1,%2,%3};" \
                 : "+f"((D)[0]), "+f"((D)[1]), "+f"((D)[2]), "+f"((D)[3]) \
                 : "r"((A)[0]), "r"((A)[1]), "r"((A)[2]), "r"((A)[3]), "r"(b0), "r"(b1))

#define CPA(sm, gm) \
    asm volatile("cp.async.cg.shared.global [%0], [%1], 16;" :: "r"(sm), "l"(gm) : "memory")
#define CPA_COMMIT asm volatile("cp.async.commit_group;" ::: "memory")
#define CPA_WAIT(n) asm volatile("cp.async.wait_group %0;" :: "n"(n) : "memory")

// swizzled byte offset inside a 128x(64B) tile: row, 16B-column
__device__ __forceinline__ uint32_t swz(int row, int c16) {
    return (uint32_t)row * 64 + (uint32_t)((c16 ^ ((row >> 1) & 3)) << 4);
}

// fp32x4 -> fp16 hi pair + fp16 residual pair
__device__ __forceinline__ void split4h(float4 v, uint32_t& h01, uint32_t& h23,
                                        uint32_t& l01, uint32_t& l23) {
    __half2 h0 = __floats2half2_rn(v.x, v.y);
    __half2 h1 = __floats2half2_rn(v.z, v.w);
    float2 f0 = __half22float2(h0);
    float2 f1 = __half22float2(h1);
    __half2 l0 = __floats2half2_rn(v.x - f0.x, v.y - f0.y);
    __half2 l1 = __floats2half2_rn(v.z - f1.x, v.w - f1.y);
    h01 = *(uint32_t*)&h0; h23 = *(uint32_t*)&h1;
    l01 = *(uint32_t*)&l0; l23 = *(uint32_t*)&l1;
}

#define ST1 24576          // gemm1 stage: Ahi(8K) + Bhi(8K) + Blo(8K); 4 stages
#define ST2 16384          // gemm2 stage: Ahi(8K) + B(8K); 4 stages

// ============== GEMM1 mainloop: 2-term (Ah·Bh + Ah·Bl), BK=32, 4-stage ==============
template <int NCH>
__device__ __forceinline__ void mainloop_2t(
    const __half* gAhi, size_t ldA,
    const __half* gBhi, const __half* gBlo, size_t ldB,
    uint32_t sbase, int tid, float acc[2][8][4])
{
    const int lane = tid & 31, w = tid >> 5;
    const int wm = (w & 3) * 32, wn = (w >> 2) * 64;
    const int rowA = wm + (lane & 15);
    const uint32_t aOff = swz(rowA, lane >> 4);
    const int rowB = wn + (lane & 7) + 8 * (lane >> 4);
    const uint32_t bOff = swz(rowB, (lane >> 3) & 1);

    const int lrow = tid >> 2, seg = tid & 3;
    const uint32_t d0 = swz(lrow, seg);
    const uint32_t d1 = swz(lrow + 64, seg);
    const __half* pA0 = gAhi + (size_t)lrow * ldA + seg * 8;
    const __half* pA1 = pA0 + 64 * ldA;
    const __half* pB0hi = gBhi + (size_t)lrow * ldB + seg * 8;
    const __half* pB1hi = pB0hi + 64 * ldB;
    const __half* pB0lo = gBlo + (size_t)lrow * ldB + seg * 8;
    const __half* pB1lo = pB0lo + 64 * ldB;

#define G1_ISSUE(buf, c) do { \
        const uint32_t t = sbase + (buf) * ST1; \
        const size_t ko = (size_t)(c) * 32; \
        CPA(t + d0,           pA0 + ko);   CPA(t + d1,           pA1 + ko); \
        CPA(t + 8192 + d0,    pB0hi + ko); CPA(t + 8192 + d1,    pB1hi + ko); \
        CPA(t + 16384 + d0,   pB0lo + ko); CPA(t + 16384 + d1,   pB1lo + ko); \
        CPA_COMMIT; \
    } while (0)

    G1_ISSUE(0, 0);
    G1_ISSUE(1, 1);
    G1_ISSUE(2, 2);

#pragma unroll 1
    for (int c = 0; c < NCH; c++) {
        if (c + 2 < NCH) { CPA_WAIT(2); }
        else if (c + 1 < NCH) { CPA_WAIT(1); }
        else { CPA_WAIT(0); }
        __syncthreads();
        if (c + 3 < NCH) {
            int buf = (c + 3) & 3;
            G1_ISSUE(buf, c + 3);
        }
        const uint32_t t0 = sbase + (c & 3) * ST1;
        const uint32_t sAhi = t0, sBhi = t0 + 8192, sBlo = t0 + 16384;
#pragma unroll
        for (int k16 = 0; k16 < 2; k16++) {
            const uint32_t kx = k16 << 5;
            uint32_t ah[2][4], bb[4][4];
            LDSM4(ah[0], sAhi + (aOff ^ kx));
            LDSM4(ah[1], sAhi + ((aOff + 1024) ^ kx));
#pragma unroll
            for (int p = 0; p < 4; p++) LDSM4(bb[p], sBhi + ((bOff + p * 1024) ^ kx));
#pragma unroll
            for (int mt = 0; mt < 2; mt++)
#pragma unroll
                for (int nt = 0; nt < 8; nt++) {
                    uint32_t b0 = bb[nt >> 1][(nt & 1) * 2];
                    uint32_t b1 = bb[nt >> 1][(nt & 1) * 2 + 1];
                    MMA(acc[mt][nt], ah[mt], b0, b1);   // hi*hi
                }
#pragma unroll
            for (int p = 0; p < 4; p++) LDSM4(bb[p], sBlo + ((bOff + p * 1024) ^ kx));
#pragma unroll
            for (int mt = 0; mt < 2; mt++)
#pragma unroll
                for (int nt = 0; nt < 8; nt++) {
                    uint32_t b0 = bb[nt >> 1][(nt & 1) * 2];
                    uint32_t b1 = bb[nt >> 1][(nt & 1) * 2 + 1];
                    MMA(acc[mt][nt], ah[mt], b0, b1);   // hi*lo
                }
        }
    }
#undef G1_ISSUE
}

// ============== GEMM2 mainloop: hi-only, BK=32, 4-stage pipeline, trans-B from g_xhi ==============
template <int NCH>
__device__ __forceinline__ void mainloop_hiT(
    const __half* gA, size_t ldA, const __half* gB,
    uint32_t sbase, int tid, float acc[2][8][4])
{
    const int lane = tid & 31, w = tid >> 5;
    const int wm = (w & 3) * 32, wn = (w >> 2) * 64;
    const int rowA = wm + (lane & 15);
    const uint32_t aOff = swz(rowA, lane >> 4);

    const int bRowL = lane & 15;
    const uint32_t bSel = (uint32_t)(lane >> 4);
    const uint32_t bUnit0 = (uint32_t)(wn >> 3);

    const int lrow = tid >> 2, seg = tid & 3;
    const uint32_t da0 = swz(lrow, seg);
    const uint32_t da1 = swz(lrow + 64, seg);
    const __half* pA0 = gA + (size_t)lrow * ldA + seg * 8;
    const __half* pA1 = pA0 + 64 * ldA;

    const int brow = tid >> 3;
    const uint32_t bu = (uint32_t)(tid & 7);
    const uint32_t db0 = (uint32_t)brow * 256 + ((bu ^ (brow & 7)) << 4);
    const uint32_t db1 = (uint32_t)brow * 256 + (((bu + 8) ^ (brow & 7)) << 4);
    const __half* pB = gB + (size_t)brow * 1024 + bu * 8;

#define G2_ISSUE(buf, c) do { \
        const uint32_t t = sbase + (buf) * ST2; \
        const size_t koA = (size_t)(c) * 32; \
        const size_t koB = (size_t)(c) * 32 * 1024; \
        CPA(t + da0,        pA0 + koA); CPA(t + da1,        pA1 + koA); \
        CPA(t + 8192 + db0, pB + koB);  CPA(t + 8192 + db1, pB + koB + 64); \
        CPA_COMMIT; \
    } while (0)

    G2_ISSUE(0, 0);
    G2_ISSUE(1, 1);
    G2_ISSUE(2, 2);

#pragma unroll 1
    for (int c = 0; c < NCH; c++) {
        if (c + 2 < NCH) { CPA_WAIT(2); }
        else if (c + 1 < NCH) { CPA_WAIT(1); }
        else { CPA_WAIT(0); }
        __syncthreads();
        if (c + 3 < NCH) {
            int buf = (c + 3) & 3;
            G2_ISSUE(buf, c + 3);
        }
        const uint32_t t0 = sbase + (c & 3) * ST2;
        const uint32_t sA = t0, sB = t0 + 8192;
#pragma unroll
        for (int k16 = 0; k16 < 2; k16++) {
            const uint32_t kx = k16 << 5;
            uint32_t ah[2][4], bb[4][4];
            LDSM4(ah[0], sA + (aOff ^ kx));
            LDSM4(ah[1], sA + ((aOff + 1024) ^ kx));
            const int rr = k16 * 16 + bRowL;
            const uint32_t rbase = (uint32_t)rr * 256;
            const uint32_t rx = (uint32_t)(rr & 7);
#pragma unroll
            for (int p = 0; p < 4; p++) {
                uint32_t unit = bUnit0 + (uint32_t)p * 2 + bSel;
                LDSM4T(bb[p], sB + rbase + ((unit ^ rx) << 4));
            }
#pragma unroll
            for (int mt = 0; mt < 2; mt++)
#pragma unroll
                for (int nt = 0; nt < 8; nt++) {
                    uint32_t b0 = bb[nt >> 1][(nt & 1) * 2];
                    uint32_t b1 = bb[nt >> 1][(nt & 1) * 2 + 1];
                    MMA(acc[mt][nt], ah[mt], b0, b1);
                }
        }
    }
#undef G2_ISSUE
}

// ---------------- fused GEMM kernel: blocks 0..511 gemm1, 512..1535 gemm2 ----------------
__global__ void __launch_bounds__(256, 2) k_gemms(
    const float* __restrict__ B1, const float* __restrict__ G1, const float* __restrict__ BE1,
    const float* __restrict__ Mu1, const float* __restrict__ Va1,
    const float* __restrict__ B2, const float* __restrict__ G2, const float* __restrict__ BE2,
    const float* __restrict__ Mu2, const float* __restrict__ Va2,
    const float* __restrict__ B3, const float* __restrict__ G3, const float* __restrict__ BE3,
    const float* __restrict__ Mu3, const float* __restrict__ Va3,
    const float* __restrict__ W4)
{
    extern __shared__ char dsm[];
    const int tid = threadIdx.x;
    const int bid = blockIdx.x;
    const uint32_t sbase = smem_u32(dsm);

    float acc[2][8][4];
#pragma unroll
    for (int mt = 0; mt < 2; mt++)
#pragma unroll
        for (int nt = 0; nt < 8; nt++)
#pragma unroll
            for (int j = 0; j < 4; j++) acc[mt][nt][j] = 0.f;

    const int lane = tid & 31, w = tid >> 5;
    const int wm = (w & 3) * 32, wn = (w >> 2) * 64;

    if (bid < 512) {
        // ---- GEMM1 + fused u/v contraction ----
        __shared__ float s_al[128], s_be[128];
        const int m0 = (bid & 127) * 128;
        const int n0 = (bid >> 7) * 128;

        if (tid < 128) {
            int n = n0 + tid;
            float bb, gg, bee, mm, vv;
            if (n < 256) { bb = B1[n]; gg = G1[n]; bee = BE1[n]; mm = Mu1[n]; vv = Va1[n]; }
            else { int o = n - 256; bb = B2[o]; gg = G2[o]; bee = BE2[o]; mm = Mu2[o]; vv = Va2[o]; }
            float a = gg * rsqrtf(vv + EPSV);
            s_al[tid] = a;
            s_be[tid] = (bb - mm) * a + bee;
        }

        mainloop_2t<32>(g_xhi + (size_t)m0 * 1024, 1024,
                        g_whi + (size_t)n0 * 1024, g_wlo + (size_t)n0 * 1024, 1024,
                        sbase, tid, acc);

        const int batch = m0 >> 9;
        const int ibase = (m0 & 511) + wm + (lane >> 2);
        const float* wsel = (n0 < 256) ? (W4 + 513) : (W4 + 1);   // theta->v, phi->u
        float* gdst = (n0 < 256) ? g_v : g_u;
        const float wg0 = wsel[ibase];
        const float wg1 = wsel[ibase + 8];
        const float wg2 = wsel[ibase + 16];
        const float wg3 = wsel[ibase + 24];
        float su[8][2];
#pragma unroll
        for (int nt = 0; nt < 8; nt++) { su[nt][0] = 0.f; su[nt][1] = 0.f; }

#pragma unroll
        for (int mt = 0; mt < 2; mt++) {
            int m = m0 + wm + mt * 16 + (lane >> 2);
            float wa = (mt == 0) ? wg0 : wg2;
            float wb = (mt == 0) ? wg1 : wg3;
#pragma unroll
            for (int nt = 0; nt < 8; nt++) {
                int nb = wn + nt * 8 + 2 * (lane & 3);
                float a0 = s_al[nb], a1 = s_al[nb + 1];
                float b0 = s_be[nb], b1 = s_be[nb + 1];
                float2 v0, v1;
                v0.x = fmaxf(fmaf(acc[mt][nt][0], a0, b0), 0.f);
                v0.y = fmaxf(fmaf(acc[mt][nt][1], a1, b1), 0.f);
                v1.x = fmaxf(fmaf(acc[mt][nt][2], a0, b0), 0.f);
                v1.y = fmaxf(fmaf(acc[mt][nt][3], a1, b1), 0.f);
                *(float2*)&g_tp[(size_t)m * 512 + n0 + nb] = v0;
                *(float2*)&g_tp[(size_t)(m + 8) * 512 + n0 + nb] = v1;
                su[nt][0] += wa * v0.x + wb * v1.x;
                su[nt][1] += wa * v0.y + wb * v1.y;
            }
        }
#pragma unroll
        for (int nt = 0; nt < 8; nt++) {
#pragma unroll
            for (int msk = 4; msk <= 16; msk <<= 1) {
                su[nt][0] += __shfl_xor_sync(0xffffffff, su[nt][0], msk);
                su[nt][1] += __shfl_xor_sync(0xffffffff, su[nt][1], msk);
            }
        }
        if (lane < 4) {
            const int kb = (n0 & 255) + wn;
#pragma unroll
            for (int nt = 0; nt < 8; nt++) {
                int k = kb + nt * 8 + 2 * lane;
                atomicAdd(&gdst[batch * 256 + k], su[nt][0]);
                atomicAdd(&gdst[batch * 256 + k + 1], su[nt][1]);
            }
        }
    } else {
        // ---- GEMM2: g_xe[b,o] += sum_p relu(bn3(W3[o,:] . X[b,:,p])) ----
        const int t = bid - 512;
        const int p0 = (t & 7) * 128;
        const int o0 = ((t >> 3) & 3) * 128;
        const int b  = t >> 5;

        mainloop_hiT<16>(g_w3hi + (size_t)o0 * 512, 512,
                         g_xhi + (size_t)b * 512 * 1024 + p0,
                         sbase, tid, acc);

#pragma unroll
        for (int mt = 0; mt < 2; mt++) {
            int o = o0 + wm + mt * 16 + (lane >> 2);
            float al0 = G3[o] * rsqrtf(Va3[o] + EPSV);
            float be0 = (B3[o] - Mu3[o]) * al0 + BE3[o];
            float al1 = G3[o + 8] * rsqrtf(Va3[o + 8] + EPSV);
            float be1 = (B3[o + 8] - Mu3[o + 8]) * al1 + BE3[o + 8];
            float s0 = 0.f, s1 = 0.f;
#pragma unroll
            for (int nt = 0; nt < 8; nt++) {
                s0 += fmaxf(fmaf(acc[mt][nt][0], al0, be0), 0.f)
                    + fmaxf(fmaf(acc[mt][nt][1], al0, be0), 0.f);
                s1 += fmaxf(fmaf(acc[mt][nt][2], al1, be1), 0.f)
                    + fmaxf(fmaf(acc[mt][nt][3], al1, be1), 0.f);
            }
            s0 += __shfl_xor_sync(0xffffffff, s0, 1);
            s0 += __shfl_xor_sync(0xffffffff, s0, 2);
            s1 += __shfl_xor_sync(0xffffffff, s1, 1);
            s1 += __shfl_xor_sync(0xffffffff, s1, 2);
            if ((lane & 3) == 0) {
                atomicAdd(&g_xe[b * 512 + o], s0);
                atomicAdd(&g_xe[b * 512 + o + 8], s1);
            }
        }
    }
}

// ---------------- prep: split X (hi only) + weights + zero accumulators ----------------
__global__ void __launch_bounds__(256) k_prep(
    const float* __restrict__ X,
    const float* __restrict__ w1, const float* __restrict__ w2, const float* __restrict__ w3)
{
    const int bid = blockIdx.x;
    const int tid = threadIdx.x;

    if (bid < 4096) {
        const int p0 = (bid & 7) * 128;
        const int c0 = ((bid >> 3) & 15) * 32;
        const int b  = bid >> 7;
        const int pj = (tid & 15) * 8;
#pragma unroll
        for (int pass = 0; pass < 2; pass++) {
            int ci = (tid >> 4) + pass * 16;
            size_t gi = ((size_t)b * 512 + c0 + ci) * 1024 + p0 + pj;
            float4 v0 = *(const float4*)(X + gi);
            float4 v1 = *(const float4*)(X + gi + 4);
            __half2 h0 = __floats2half2_rn(v0.x, v0.y);
            __half2 h1 = __floats2half2_rn(v0.z, v0.w);
            __half2 h2 = __floats2half2_rn(v1.x, v1.y);
            __half2 h3 = __floats2half2_rn(v1.z, v1.w);
            *(uint4*)&g_xhi[gi] = make_uint4(*(uint32_t*)&h0, *(uint32_t*)&h1,
                                             *(uint32_t*)&h2, *(uint32_t*)&h3);
        }
    } else {
        int flat = (bid - 4096) * 256 + tid;
        if (flat < 16384) g_xe[flat] = 0.f;
        if (flat < 8192) { g_u[flat] = 0.f; g_v[flat] = 0.f; }

        int idx = flat * 8;
        uint32_t h01, h23, l01, l23, h01b, h23b, l01b, l23b;
        if (idx < 512 * 1024) {
            int n = idx >> 10, k = idx & 1023;
            const float* src = (n < 256) ? (w1 + (size_t)n * 1024 + k)
                                         : (w2 + (size_t)(n - 256) * 1024 + k);
            float4 v0 = *(const float4*)src;
            float4 v1 = *(const float4*)(src + 4);
            split4h(v0, h01, h23, l01, l23);
            split4h(v1, h01b, h23b, l01b, l23b);
            *(uint4*)&g_whi[idx] = make_uint4(h01, h23, h01b, h23b);
            *(uint4*)&g_wlo[idx] = make_uint4(l01, l23, l01b, l23b);
        } else if (idx < 512 * 1024 + 512 * 512) {
            int j = idx - 512 * 1024;
            float4 v0 = *(const float4*)(w3 + j);
            float4 v1 = *(const float4*)(w3 + j + 4);
            __half2 h0 = __floats2half2_rn(v0.x, v0.y);
            __half2 h1 = __floats2half2_rn(v0.z, v0.w);
            __half2 h2 = __floats2half2_rn(v1.x, v1.y);
            __half2 h3 = __floats2half2_rn(v1.z, v1.w);
            *(uint4*)&g_w3hi[j] = make_uint4(*(uint32_t*)&h0, *(uint32_t*)&h1,
                                             *(uint32_t*)&h2, *(uint32_t*)&h3);
        }
    }
}

// ---------------- final: warp-per-row logits, sigmoid, gate ----------------
__global__ void __launch_bounds__(256) k_final(
    const float* __restrict__ X, const float* __restrict__ w4,
    const float* __restrict__ b4, float* __restrict__ OUT)
{
    const int tid = threadIdx.x;
    const int lane = tid & 31;
    const int m = blockIdx.x * 8 + (tid >> 5);
    const int b = m >> 9;

    const float* tp = g_tp + (size_t)m * 512;
    const float* uu = g_u + b * 256;
    const float* vv = g_v + b * 256;
    float s = 0.f;
#pragma unroll
    for (int j = 0; j < 8; j++) {
        int k = lane + 32 * j;
        s = fmaf(uu[k], tp[k], s);
        s = fmaf(vv[k], tp[256 + k], s);
    }
#pragma unroll
    for (int o = 16; o; o >>= 1) s += __shfl_xor_sync(0xffffffff, s, o);

    float xe = g_xe[m] * (1.f / 1024.f);
    float logit = w4[0] * xe + s + b4[0];
    float a = 1.f / (1.f + expf(-logit));

    const float4* xin = (const float4*)(X + (size_t)m * 1024);
    float4* xo = (float4*)(OUT + (size_t)m * 1024);
#pragma unroll
    for (int it = 0; it < 8; it++) {
        float4 v = xin[lane + 32 * it];
        v.x *= a; v.y *= a; v.z *= a; v.w *= a;
        xo[lane + 32 * it] = v;
    }
}

// ---------------- launch ----------------
#define DSMEM (4 * ST1)   // 98304: gemm1 4 x 24KB stages; gemm2 4 x 16KB within this

extern "C" void kernel_launch(void* const* d_in, const int* in_sizes, int n_in,
                              void* d_out, int out_size) {
    const float* x   = (const float*)d_in[0];
    const float* w1  = (const float*)d_in[1];
    const float* b1  = (const float*)d_in[2];
    const float* g1  = (const float*)d_in[3];
    const float* be1 = (const float*)d_in[4];
    const float* m1  = (const float*)d_in[5];
    const float* v1  = (const float*)d_in[6];
    const float* w2  = (const float*)d_in[7];
    const float* b2  = (const float*)d_in[8];
    const float* g2  = (const float*)d_in[9];
    const float* be2 = (const float*)d_in[10];
    const float* m2  = (const float*)d_in[11];
    const float* v2  = (const float*)d_in[12];
    const float* w3  = (const float*)d_in[13];
    const float* b3  = (const float*)d_in[14];
    const float* g3  = (const float*)d_in[15];
    const float* be3 = (const float*)d_in[16];
    const float* m3  = (const float*)d_in[17];
    const float* v3  = (const float*)d_in[18];
    const float* w4  = (const float*)d_in[19];
    const float* b4  = (const float*)d_in[20];
    float* out = (float*)d_out;

    cudaFuncSetAttribute(k_gemms, cudaFuncAttributeMaxDynamicSharedMemorySize, DSMEM);

    k_prep<<<4096 + 384, 256>>>(x, w1, w2, w3);
    k_gemms<<<1536, 256, DSMEM>>>(b1, g1, be1, m1, v1,
                                  b2, g2, be2, m2, v2,
                                  b3, g3, be3, m3, v3, w4);
    k_final<<<2048, 256>>>(x, w4, b4, out);
}

// round 17
// speedup vs baseline: 1.0152x; 1.0152x over previous
#include <cuda_runtime.h>
#include <cuda_fp16.h>
#include <cstdint>
#include <math.h>

#define EPSV 1e-5f

// ---------------- scratch (device globals; no allocs allowed) ----------------
__device__ float g_tp[16384 * 512];              // 32 MB theta||phi (fp32)
__device__ __half g_xhi[16384 * 1024];           // X hi  [b*c][p]
__device__ __half g_whi[512 * 1024];             // w1||w2 hi
__device__ __half g_wlo[512 * 1024];             // w1||w2 lo (residual)
__device__ __half g_w3hi[512 * 512];
__device__ float g_xe[16384];
__device__ float g_u[8192];
__device__ float g_v[8192];

__device__ __forceinline__ uint32_t smem_u32(const void* p) {
    uint32_t a;
    asm("{ .reg .u64 t; cvta.to.shared.u64 t, %1; cvt.u32.u64 %0, t; }" : "=r"(a) : "l"(p));
    return a;
}

#define LDSM4(R, addr) \
    asm volatile("ldmatrix.sync.aligned.m8n8.x4.shared.b16 {%0,%1,%2,%3}, [%4];" \
                 : "=r"((R)[0]), "=r"((R)[1]), "=r"((R)[2]), "=r"((R)[3]) : "r"(addr))

#define LDSM4T(R, addr) \
    asm volatile("ldmatrix.sync.aligned.m8n8.x4.trans.shared.b16 {%0,%1,%2,%3}, [%4];" \
                 : "=r"((R)[0]), "=r"((R)[1]), "=r"((R)[2]), "=r"((R)[3]) : "r"(addr))

#define MMA(D, A, b0, b1) \
    asm volatile("mma.sync.aligned.m16n8k16.row.col.f32.f16.f16.f32 " \
                 "{%0,%1,%2,%3},{%4,%5,%6,%7},{%8,%9},{%0,%1,%2,%3};" \
                 : "+f"((D)[0]), "+f"((D)[1]), "+f"((D)[2]), "+f"((D)[3]) \
                 : "r"((A)[0]), "r"((A)[1]), "r"((A)[2]), "r"((A)[3]), "r"(b0), "r"(b1))

#define CPA(sm, gm) \
    asm volatile("cp.async.cg.shared.global [%0], [%1], 16;" :: "r"(sm), "l"(gm) : "memory")
#define CPA_COMMIT asm volatile("cp.async.commit_group;" ::: "memory")
#define CPA_WAIT(n) asm volatile("cp.async.wait_group %0;" :: "n"(n) : "memory")

// swizzled byte offset inside a 128x(64B) tile: row, 16B-column
__device__ __forceinline__ uint32_t swz(int row, int c16) {
    return (uint32_t)row * 64 + (uint32_t)((c16 ^ ((row >> 1) & 3)) << 4);
}

// fp32x4 -> fp16 hi pair + fp16 residual pair
__device__ __forceinline__ void split4h(float4 v, uint32_t& h01, uint32_t& h23,
                                        uint32_t& l01, uint32_t& l23) {
    __half2 h0 = __floats2half2_rn(v.x, v.y);
    __half2 h1 = __floats2half2_rn(v.z, v.w);
    float2 f0 = __half22float2(h0);
    float2 f1 = __half22float2(h1);
    __half2 l0 = __floats2half2_rn(v.x - f0.x, v.y - f0.y);
    __half2 l1 = __floats2half2_rn(v.z - f1.x, v.w - f1.y);
    h01 = *(uint32_t*)&h0; h23 = *(uint32_t*)&h1;
    l01 = *(uint32_t*)&l0; l23 = *(uint32_t*)&l1;
}

#define ST1 24576          // gemm1 stage: Ahi(8K) + Bhi(8K) + Blo(8K); 3 stages
#define ST2 16384          // gemm2 stage: Ahi(8K) + B(8K); 4 stages

// ============== GEMM1 mainloop: 2-term, BK=32, 3-stage, 2x4 warp grid ==============
// warp tile: 64 rows x 32 cols; per k16: 4 A-LDSM + 2+2 B-LDSM, 32 MMA
template <int NCH>
__device__ __forceinline__ void mainloop_2t(
    const __half* gAhi, size_t ldA,
    const __half* gBhi, const __half* gBlo, size_t ldB,
    uint32_t sbase, int tid, float acc[4][4][4])
{
    const int lane = tid & 31, w = tid >> 5;
    const int wm = (w & 1) * 64, wn = (w >> 1) * 32;
    const int rowA = wm + (lane & 15);
    const uint32_t aOff = swz(rowA, lane >> 4);
    const int rowB = wn + (lane & 7) + 8 * (lane >> 4);
    const uint32_t bOff = swz(rowB, (lane >> 3) & 1);

    const int lrow = tid >> 2, seg = tid & 3;
    const uint32_t d0 = swz(lrow, seg);
    const uint32_t d1 = swz(lrow + 64, seg);
    const __half* pA0 = gAhi + (size_t)lrow * ldA + seg * 8;
    const __half* pA1 = pA0 + 64 * ldA;
    const __half* pB0hi = gBhi + (size_t)lrow * ldB + seg * 8;
    const __half* pB1hi = pB0hi + 64 * ldB;
    const __half* pB0lo = gBlo + (size_t)lrow * ldB + seg * 8;
    const __half* pB1lo = pB0lo + 64 * ldB;

#define G1_ISSUE(buf, c) do { \
        const uint32_t t = sbase + (buf) * ST1; \
        const size_t ko = (size_t)(c) * 32; \
        CPA(t + d0,           pA0 + ko);   CPA(t + d1,           pA1 + ko); \
        CPA(t + 8192 + d0,    pB0hi + ko); CPA(t + 8192 + d1,    pB1hi + ko); \
        CPA(t + 16384 + d0,   pB0lo + ko); CPA(t + 16384 + d1,   pB1lo + ko); \
        CPA_COMMIT; \
    } while (0)

    G1_ISSUE(0, 0);
    G1_ISSUE(1, 1);

#pragma unroll 1
    for (int c = 0; c < NCH; c++) {
        if (c + 1 < NCH) { CPA_WAIT(1); } else { CPA_WAIT(0); }
        __syncthreads();
        if (c + 2 < NCH) {
            int buf = (c + 2) % 3;
            G1_ISSUE(buf, c + 2);
        }
        const uint32_t t0 = sbase + (c % 3) * ST1;
        const uint32_t sAhi = t0, sBhi = t0 + 8192, sBlo = t0 + 16384;
#pragma unroll
        for (int k16 = 0; k16 < 2; k16++) {
            const uint32_t kx = k16 << 5;
            uint32_t ah[4][4], bb[2][4];
#pragma unroll
            for (int mt = 0; mt < 4; mt++)
                LDSM4(ah[mt], sAhi + ((aOff + mt * 1024) ^ kx));
#pragma unroll
            for (int p = 0; p < 2; p++) LDSM4(bb[p], sBhi + ((bOff + p * 1024) ^ kx));
#pragma unroll
            for (int mt = 0; mt < 4; mt++)
#pragma unroll
                for (int nt = 0; nt < 4; nt++) {
                    uint32_t b0 = bb[nt >> 1][(nt & 1) * 2];
                    uint32_t b1 = bb[nt >> 1][(nt & 1) * 2 + 1];
                    MMA(acc[mt][nt], ah[mt], b0, b1);   // hi*hi
                }
#pragma unroll
            for (int p = 0; p < 2; p++) LDSM4(bb[p], sBlo + ((bOff + p * 1024) ^ kx));
#pragma unroll
            for (int mt = 0; mt < 4; mt++)
#pragma unroll
                for (int nt = 0; nt < 4; nt++) {
                    uint32_t b0 = bb[nt >> 1][(nt & 1) * 2];
                    uint32_t b1 = bb[nt >> 1][(nt & 1) * 2 + 1];
                    MMA(acc[mt][nt], ah[mt], b0, b1);   // hi*lo
                }
        }
    }
#undef G1_ISSUE
}

// ============== GEMM2 mainloop: hi-only, BK=32, 4-stage pipeline, trans-B from g_xhi ==============
template <int NCH>
__device__ __forceinline__ void mainloop_hiT(
    const __half* gA, size_t ldA, const __half* gB,
    uint32_t sbase, int tid, float acc[2][8][4])
{
    const int lane = tid & 31, w = tid >> 5;
    const int wm = (w & 3) * 32, wn = (w >> 2) * 64;
    const int rowA = wm + (lane & 15);
    const uint32_t aOff = swz(rowA, lane >> 4);

    const int bRowL = lane & 15;
    const uint32_t bSel = (uint32_t)(lane >> 4);
    const uint32_t bUnit0 = (uint32_t)(wn >> 3);

    const int lrow = tid >> 2, seg = tid & 3;
    const uint32_t da0 = swz(lrow, seg);
    const uint32_t da1 = swz(lrow + 64, seg);
    const __half* pA0 = gA + (size_t)lrow * ldA + seg * 8;
    const __half* pA1 = pA0 + 64 * ldA;

    const int brow = tid >> 3;
    const uint32_t bu = (uint32_t)(tid & 7);
    const uint32_t db0 = (uint32_t)brow * 256 + ((bu ^ (brow & 7)) << 4);
    const uint32_t db1 = (uint32_t)brow * 256 + (((bu + 8) ^ (brow & 7)) << 4);
    const __half* pB = gB + (size_t)brow * 1024 + bu * 8;

#define G2_ISSUE(buf, c) do { \
        const uint32_t t = sbase + (buf) * ST2; \
        const size_t koA = (size_t)(c) * 32; \
        const size_t koB = (size_t)(c) * 32 * 1024; \
        CPA(t + da0,        pA0 + koA); CPA(t + da1,        pA1 + koA); \
        CPA(t + 8192 + db0, pB + koB);  CPA(t + 8192 + db1, pB + koB + 64); \
        CPA_COMMIT; \
    } while (0)

    G2_ISSUE(0, 0);
    G2_ISSUE(1, 1);
    G2_ISSUE(2, 2);

#pragma unroll 1
    for (int c = 0; c < NCH; c++) {
        if (c + 2 < NCH) { CPA_WAIT(2); }
        else if (c + 1 < NCH) { CPA_WAIT(1); }
        else { CPA_WAIT(0); }
        __syncthreads();
        if (c + 3 < NCH) {
            int buf = (c + 3) & 3;
            G2_ISSUE(buf, c + 3);
        }
        const uint32_t t0 = sbase + (c & 3) * ST2;
        const uint32_t sA = t0, sB = t0 + 8192;
#pragma unroll
        for (int k16 = 0; k16 < 2; k16++) {
            const uint32_t kx = k16 << 5;
            uint32_t ah[2][4], bb[4][4];
            LDSM4(ah[0], sA + (aOff ^ kx));
            LDSM4(ah[1], sA + ((aOff + 1024) ^ kx));
            const int rr = k16 * 16 + bRowL;
            const uint32_t rbase = (uint32_t)rr * 256;
            const uint32_t rx = (uint32_t)(rr & 7);
#pragma unroll
            for (int p = 0; p < 4; p++) {
                uint32_t unit = bUnit0 + (uint32_t)p * 2 + bSel;
                LDSM4T(bb[p], sB + rbase + ((unit ^ rx) << 4));
            }
#pragma unroll
            for (int mt = 0; mt < 2; mt++)
#pragma unroll
                for (int nt = 0; nt < 8; nt++) {
                    uint32_t b0 = bb[nt >> 1][(nt & 1) * 2];
                    uint32_t b1 = bb[nt >> 1][(nt & 1) * 2 + 1];
                    MMA(acc[mt][nt], ah[mt], b0, b1);
                }
        }
    }
#undef G2_ISSUE
}

// ---------------- fused GEMM kernel: blocks 0..511 gemm1, 512..1535 gemm2 ----------------
__global__ void __launch_bounds__(256, 2) k_gemms(
    const float* __restrict__ B1, const float* __restrict__ G1, const float* __restrict__ BE1,
    const float* __restrict__ Mu1, const float* __restrict__ Va1,
    const float* __restrict__ B2, const float* __restrict__ G2, const float* __restrict__ BE2,
    const float* __restrict__ Mu2, const float* __restrict__ Va2,
    const float* __restrict__ B3, const float* __restrict__ G3, const float* __restrict__ BE3,
    const float* __restrict__ Mu3, const float* __restrict__ Va3,
    const float* __restrict__ W4)
{
    extern __shared__ char dsm[];
    const int tid = threadIdx.x;
    const int bid = blockIdx.x;
    const uint32_t sbase = smem_u32(dsm);
    const int lane = tid & 31, w = tid >> 5;

    if (bid < 512) {
        // ---- GEMM1 (2x4 warp grid) + fused u/v contraction ----
        __shared__ float s_al[128], s_be[128];
        const int m0 = (bid & 127) * 128;
        const int n0 = (bid >> 7) * 128;
        const int wm = (w & 1) * 64, wn = (w >> 1) * 32;

        if (tid < 128) {
            int n = n0 + tid;
            float bb, gg, bee, mm, vv;
            if (n < 256) { bb = B1[n]; gg = G1[n]; bee = BE1[n]; mm = Mu1[n]; vv = Va1[n]; }
            else { int o = n - 256; bb = B2[o]; gg = G2[o]; bee = BE2[o]; mm = Mu2[o]; vv = Va2[o]; }
            float a = gg * rsqrtf(vv + EPSV);
            s_al[tid] = a;
            s_be[tid] = (bb - mm) * a + bee;
        }

        float acc[4][4][4];
#pragma unroll
        for (int mt = 0; mt < 4; mt++)
#pragma unroll
            for (int nt = 0; nt < 4; nt++)
#pragma unroll
                for (int j = 0; j < 4; j++) acc[mt][nt][j] = 0.f;

        mainloop_2t<32>(g_xhi + (size_t)m0 * 1024, 1024,
                        g_whi + (size_t)n0 * 1024, g_wlo + (size_t)n0 * 1024, 1024,
                        sbase, tid, acc);

        const int batch = m0 >> 9;
        const int ibase = (m0 & 511) + wm + (lane >> 2);
        const float* wsel = (n0 < 256) ? (W4 + 513) : (W4 + 1);   // theta->v, phi->u
        float* gdst = (n0 < 256) ? g_v : g_u;
        float wg[4][2];
#pragma unroll
        for (int mt = 0; mt < 4; mt++) {
            wg[mt][0] = wsel[ibase + mt * 16];
            wg[mt][1] = wsel[ibase + mt * 16 + 8];
        }
        float su[4][2];
#pragma unroll
        for (int nt = 0; nt < 4; nt++) { su[nt][0] = 0.f; su[nt][1] = 0.f; }

#pragma unroll
        for (int mt = 0; mt < 4; mt++) {
            int m = m0 + wm + mt * 16 + (lane >> 2);
            float wa = wg[mt][0], wb = wg[mt][1];
#pragma unroll
            for (int nt = 0; nt < 4; nt++) {
                int nb = wn + nt * 8 + 2 * (lane & 3);
                float a0 = s_al[nb], a1 = s_al[nb + 1];
                float b0 = s_be[nb], b1 = s_be[nb + 1];
                float2 v0, v1;
                v0.x = fmaxf(fmaf(acc[mt][nt][0], a0, b0), 0.f);
                v0.y = fmaxf(fmaf(acc[mt][nt][1], a1, b1), 0.f);
                v1.x = fmaxf(fmaf(acc[mt][nt][2], a0, b0), 0.f);
                v1.y = fmaxf(fmaf(acc[mt][nt][3], a1, b1), 0.f);
                *(float2*)&g_tp[(size_t)m * 512 + n0 + nb] = v0;
                *(float2*)&g_tp[(size_t)(m + 8) * 512 + n0 + nb] = v1;
                su[nt][0] += wa * v0.x + wb * v1.x;
                su[nt][1] += wa * v0.y + wb * v1.y;
            }
        }
#pragma unroll
        for (int nt = 0; nt < 4; nt++) {
#pragma unroll
            for (int msk = 4; msk <= 16; msk <<= 1) {
                su[nt][0] += __shfl_xor_sync(0xffffffff, su[nt][0], msk);
                su[nt][1] += __shfl_xor_sync(0xffffffff, su[nt][1], msk);
            }
        }
        if (lane < 4) {
            const int kb = (n0 & 255) + wn;
#pragma unroll
            for (int nt = 0; nt < 4; nt++) {
                int k = kb + nt * 8 + 2 * lane;
                atomicAdd(&gdst[batch * 256 + k], su[nt][0]);
                atomicAdd(&gdst[batch * 256 + k + 1], su[nt][1]);
            }
        }
    } else {
        // ---- GEMM2: g_xe[b,o] += sum_p relu(bn3(W3[o,:] . X[b,:,p])) ----
        const int t = bid - 512;
        const int p0 = (t & 7) * 128;
        const int o0 = ((t >> 3) & 3) * 128;
        const int b  = t >> 5;
        const int wm = (w & 3) * 32;

        float acc[2][8][4];
#pragma unroll
        for (int mt = 0; mt < 2; mt++)
#pragma unroll
            for (int nt = 0; nt < 8; nt++)
#pragma unroll
                for (int j = 0; j < 4; j++) acc[mt][nt][j] = 0.f;

        mainloop_hiT<16>(g_w3hi + (size_t)o0 * 512, 512,
                         g_xhi + (size_t)b * 512 * 1024 + p0,
                         sbase, tid, acc);

#pragma unroll
        for (int mt = 0; mt < 2; mt++) {
            int o = o0 + wm + mt * 16 + (lane >> 2);
            float al0 = G3[o] * rsqrtf(Va3[o] + EPSV);
            float be0 = (B3[o] - Mu3[o]) * al0 + BE3[o];
            float al1 = G3[o + 8] * rsqrtf(Va3[o + 8] + EPSV);
            float be1 = (B3[o + 8] - Mu3[o + 8]) * al1 + BE3[o + 8];
            float s0 = 0.f, s1 = 0.f;
#pragma unroll
            for (int nt = 0; nt < 8; nt++) {
                s0 += fmaxf(fmaf(acc[mt][nt][0], al0, be0), 0.f)
                    + fmaxf(fmaf(acc[mt][nt][1], al0, be0), 0.f);
                s1 += fmaxf(fmaf(acc[mt][nt][2], al1, be1), 0.f)
                    + fmaxf(fmaf(acc[mt][nt][3], al1, be1), 0.f);
            }
            s0 += __shfl_xor_sync(0xffffffff, s0, 1);
            s0 += __shfl_xor_sync(0xffffffff, s0, 2);
            s1 += __shfl_xor_sync(0xffffffff, s1, 1);
            s1 += __shfl_xor_sync(0xffffffff, s1, 2);
            if ((lane & 3) == 0) {
                atomicAdd(&g_xe[b * 512 + o], s0);
                atomicAdd(&g_xe[b * 512 + o + 8], s1);
            }
        }
    }
}

// ---------------- prep: split X (hi only) + weights + zero accumulators ----------------
__global__ void __launch_bounds__(256) k_prep(
    const float* __restrict__ X,
    const float* __restrict__ w1, const float* __restrict__ w2, const float* __restrict__ w3)
{
    const int bid = blockIdx.x;
    const int tid = threadIdx.x;

    if (bid < 4096) {
        const int p0 = (bid & 7) * 128;
        const int c0 = ((bid >> 3) & 15) * 32;
        const int b  = bid >> 7;
        const int pj = (tid & 15) * 8;
#pragma unroll
        for (int pass = 0; pass < 2; pass++) {
            int ci = (tid >> 4) + pass * 16;
            size_t gi = ((size_t)b * 512 + c0 + ci) * 1024 + p0 + pj;
            float4 v0 = *(const float4*)(X + gi);
            float4 v1 = *(const float4*)(X + gi + 4);
            __half2 h0 = __floats2half2_rn(v0.x, v0.y);
            __half2 h1 = __floats2half2_rn(v0.z, v0.w);
            __half2 h2 = __floats2half2_rn(v1.x, v1.y);
            __half2 h3 = __floats2half2_rn(v1.z, v1.w);
            *(uint4*)&g_xhi[gi] = make_uint4(*(uint32_t*)&h0, *(uint32_t*)&h1,
                                             *(uint32_t*)&h2, *(uint32_t*)&h3);
        }
    } else {
        int flat = (bid - 4096) * 256 + tid;
        if (flat < 16384) g_xe[flat] = 0.f;
        if (flat < 8192) { g_u[flat] = 0.f; g_v[flat] = 0.f; }

        int idx = flat * 8;
        uint32_t h01, h23, l01, l23, h01b, h23b, l01b, l23b;
        if (idx < 512 * 1024) {
            int n = idx >> 10, k = idx & 1023;
            const float* src = (n < 256) ? (w1 + (size_t)n * 1024 + k)
                                         : (w2 + (size_t)(n - 256) * 1024 + k);
            float4 v0 = *(const float4*)src;
            float4 v1 = *(const float4*)(src + 4);
            split4h(v0, h01, h23, l01, l23);
            split4h(v1, h01b, h23b, l01b, l23b);
            *(uint4*)&g_whi[idx] = make_uint4(h01, h23, h01b, h23b);
            *(uint4*)&g_wlo[idx] = make_uint4(l01, l23, l01b, l23b);
        } else if (idx < 512 * 1024 + 512 * 512) {
            int j = idx - 512 * 1024;
            float4 v0 = *(const float4*)(w3 + j);
            float4 v1 = *(const float4*)(w3 + j + 4);
            __half2 h0 = __floats2half2_rn(v0.x, v0.y);
            __half2 h1 = __floats2half2_rn(v0.z, v0.w);
            __half2 h2 = __floats2half2_rn(v1.x, v1.y);
            __half2 h3 = __floats2half2_rn(v1.z, v1.w);
            *(uint4*)&g_w3hi[j] = make_uint4(*(uint32_t*)&h0, *(uint32_t*)&h1,
                                             *(uint32_t*)&h2, *(uint32_t*)&h3);
        }
    }
}

// ---------------- final: warp-per-row logits, sigmoid, gate ----------------
__global__ void __launch_bounds__(256) k_final(
    const float* __restrict__ X, const float* __restrict__ w4,
    const float* __restrict__ b4, float* __restrict__ OUT)
{
    const int tid = threadIdx.x;
    const int lane = tid & 31;
    const int m = blockIdx.x * 8 + (tid >> 5);
    const int b = m >> 9;

    const float* tp = g_tp + (size_t)m * 512;
    const float* uu = g_u + b * 256;
    const float* vv = g_v + b * 256;
    float s = 0.f;
#pragma unroll
    for (int j = 0; j < 8; j++) {
        int k = lane + 32 * j;
        s = fmaf(uu[k], tp[k], s);
        s = fmaf(vv[k], tp[256 + k], s);
    }
#pragma unroll
    for (int o = 16; o; o >>= 1) s += __shfl_xor_sync(0xffffffff, s, o);

    float xe = g_xe[m] * (1.f / 1024.f);
    float logit = w4[0] * xe + s + b4[0];
    float a = 1.f / (1.f + expf(-logit));

    const float4* xin = (const float4*)(X + (size_t)m * 1024);
    float4* xo = (float4*)(OUT + (size_t)m * 1024);
#pragma unroll
    for (int it = 0; it < 8; it++) {
        float4 v = xin[lane + 32 * it];
        v.x *= a; v.y *= a; v.z *= a; v.w *= a;
        xo[lane + 32 * it] = v;
    }
}

// ---------------- launch ----------------
#define DSMEM (3 * ST1)   // 73728: gemm1 3 x 24KB; gemm2 4 x 16KB = 65536 within this

extern "C" void kernel_launch(void* const* d_in, const int* in_sizes, int n_in,
                              void* d_out, int out_size) {
    const float* x   = (const float*)d_in[0];
    const float* w1  = (const float*)d_in[1];
    const float* b1  = (const float*)d_in[2];
    const float* g1  = (const float*)d_in[3];
    const float* be1 = (const float*)d_in[4];
    const float* m1  = (const float*)d_in[5];
    const float* v1  = (const float*)d_in[6];
    const float* w2  = (const float*)d_in[7];
    const float* b2  = (const float*)d_in[8];
    const float* g2  = (const float*)d_in[9];
    const float* be2 = (const float*)d_in[10];
    const float* m2  = (const float*)d_in[11];
    const float* v2  = (const float*)d_in[12];
    const float* w3  = (const float*)d_in[13];
    const float* b3  = (const float*)d_in[14];
    const float* g3  = (const float*)d_in[15];
    const float* be3 = (const float*)d_in[16];
    const float* m3  = (const float*)d_in[17];
    const float* v3  = (const float*)d_in[18];
    const float* w4  = (const float*)d_in[19];
    const float* b4  = (const float*)d_in[20];
    float* out = (float*)d_out;

    cudaFuncSetAttribute(k_gemms, cudaFuncAttributeMaxDynamicSharedMemorySize, DSMEM);

    k_prep<<<4096 + 384, 256>>>(x, w1, w2, w3);
    k_gemms<<<1536, 256, DSMEM>>>(b1, g1, be1, m1, v1,
                                  b2, g2, be2, m2, v2,
                                  b3, g3, be3, m3, v3, w4);
    k_final<<<2048, 256>>>(x, w4, b4, out);
}